// round 14
// baseline (speedup 1.0000x reference)
#include <cuda_runtime.h>
#include <math.h>

// Problem constants (fixed by reference: x = (4, 64, 128, 128) fp32)
#define HH 128
#define WW 128
#define BB 4

// Scratch (allocation-free: __device__ globals)
__device__ float g_A[BB * 128 * HH * WW];        // 32 MB ping
__device__ float g_B[BB * 128 * HH * WW];        // 32 MB pong
__device__ float g_off[BB * 18 * HH * WW];       // offsets
__device__ float g_wtc[3][128 * 9 * 128];        // per-stage transposed conv weights
__device__ float g_wto[3][128 * 9 * 24];         // per-stage transposed offset weights
__device__ float g_wtd[3][128 * 9 * 128];        // per-stage transposed deform weights

typedef unsigned long long u64;

// Packed fp32x2 ops (Blackwell FFMA2 — only reachable via PTX)
#define FMA2(d, a, b, c) \
    asm("fma.rn.f32x2 %0, %1, %2, %3;" : "=l"(d) : "l"(a), "l"(b), "l"(c))
#define PACKDUP(out, f) \
    asm("mov.b64 %0, {%1, %1};" : "=l"(out) : "r"(__float_as_uint(f)))
#define UNPACK2(lo, hi, in) \
    asm("mov.b64 {%0, %1}, %2;" : "=r"(lo), "=r"(hi) : "l"(in))

// cp.async (LDGSTS)
#define CP_ASYNC4(dst_s, src_g, szr) \
    asm volatile("cp.async.ca.shared.global [%0], [%1], 4, %2;" \
                 :: "r"(dst_s), "l"(src_g), "r"(szr))
#define CP_ASYNC16(dst_s, src_g) \
    asm volatile("cp.async.ca.shared.global [%0], [%1], 16;" \
                 :: "r"(dst_s), "l"(src_g))
#define CP_ASYNC16Z(dst_s, src_g, szr) \
    asm volatile("cp.async.ca.shared.global [%0], [%1], 16, %2;" \
                 :: "r"(dst_s), "l"(src_g), "r"(szr))
#define CP_COMMIT() asm volatile("cp.async.commit_group;")
#define CP_WAIT0()  asm volatile("cp.async.wait_group 0;")

__device__ __forceinline__ unsigned s2u(const void* p) {
    return (unsigned)__cvta_generic_to_shared(p);
}
__device__ __forceinline__ float lrelu(float v) { return v >= 0.f ? v : 0.2f * v; }

// ---------------------------------------------------------------------------
// One prep kernel does ALL 9 weight transposes (they depend only on inputs).
// ---------------------------------------------------------------------------
struct PrepJobs {
    const float* src[9];
    float*       dst[9];
    int C9[9], O[9], OP[9];
};

__global__ void prep_kernel(PrepJobs jobs)
{
    int job = blockIdx.y;
    int C9 = jobs.C9[job], O = jobs.O[job], OP = jobs.OP[job];
    int n = C9 * OP;
    const float* src = jobs.src[job];
    float* dst = jobs.dst[job];
    for (int idx = blockIdx.x * 256 + threadIdx.x; idx < n; idx += gridDim.x * 256) {
        int j = idx / OP;
        int o = idx - j * OP;
        dst[idx] = (o < O) ? src[o * C9 + j] : 0.f;
    }
}

// ---------------------------------------------------------------------------
// Plain 3x3 conv (R10 measured-best form — untouched).
// ---------------------------------------------------------------------------
template<int CIN, int OCB, bool RELU>
__global__ __launch_bounds__(128, 5)
void conv3x3_kernel(const float* __restrict__ x, const float* __restrict__ wt,
                    const float* __restrict__ bias, float* __restrict__ y,
                    int Cout, int OP, int n_ocb)
{
    __shared__ float w_s[2][36][OCB];
    __shared__ __align__(16) float in_s[2][4][18][40];
    // layout per row: col 3 = gx bx-1, cols 4..35 = bx..bx+31, col 36 = bx+32

    const int t   = threadIdx.x;
    const int lx  = t & 7;
    const int ly  = t >> 3;
    const int bx  = blockIdx.x * 32;
    const int by  = blockIdx.y * 16;
    const int b   = blockIdx.z / n_ocb;
    const int ocb = blockIdx.z % n_ocb;
    const int oc0 = ocb * OCB;

    const float* xb = x + b * CIN * HH * WW;

    u64 acc[OCB / 2][4];
    #pragma unroll
    for (int q = 0; q < OCB / 2; q++)
        #pragma unroll
        for (int p = 0; p < 4; p++) acc[q][p] = 0ull;

    auto load_chunk = [&](int c0, int bi) {
        const float* xc = xb + c0 * HH * WW;
        for (int i = t; i < 4 * 18 * 8; i += 128) {
            int cc  = i / 144;
            int rem = i - cc * 144;
            int r   = rem >> 3;
            int q   = rem & 7;
            int gy  = by - 1 + r;
            bool ok = (unsigned)gy < (unsigned)HH;
            const float* src = xc + cc * HH * WW + (ok ? gy * WW + bx + q * 4 : 0);
            int sz = ok ? 16 : 0;
            CP_ASYNC16Z(s2u(&in_s[bi][cc][r][4 + q * 4]), src, sz);
        }
        for (int i = t; i < 4 * 18 * 2; i += 128) {
            int cc   = i / 36;
            int rem  = i - cc * 36;
            int r    = rem >> 1;
            int side = rem & 1;
            int gy   = by - 1 + r;
            int gx   = side ? bx + 32 : bx - 1;
            bool ok  = ((unsigned)gy < (unsigned)HH) & ((unsigned)gx < (unsigned)WW);
            const float* src = xc + cc * HH * WW + (ok ? gy * WW + gx : 0);
            int sz = ok ? 4 : 0;
            CP_ASYNC4(s2u(&in_s[bi][cc][r][side ? 36 : 3]), src, sz);
        }
        for (int i = t; i < 36 * (OCB / 4); i += 128) {
            int row = i / (OCB / 4);
            int q   = i - row * (OCB / 4);
            CP_ASYNC16(s2u(&w_s[bi][row][q * 4]),
                       &wt[(c0 * 9 + row) * OP + oc0 + q * 4]);
        }
    };

    load_chunk(0, 0);
    CP_COMMIT();

    int buf = 0;
    for (int c0 = 0; c0 < CIN; c0 += 4) {
        CP_WAIT0();
        __syncthreads();
        if (c0 + 4 < CIN) { load_chunk(c0 + 4, buf ^ 1); CP_COMMIT(); }

        #pragma unroll
        for (int cc = 0; cc < 4; cc++) {
            #pragma unroll
            for (int ry = 0; ry < 3; ry++) {
                float e0 = in_s[buf][cc][ly + ry][lx * 4 + 3];
                float4 rm = *(const float4*)&in_s[buf][cc][ly + ry][lx * 4 + 4];
                float e5 = in_s[buf][cc][ly + ry][lx * 4 + 8];
                float rowv[6] = {e0, rm.x, rm.y, rm.z, rm.w, e5};
                #pragma unroll
                for (int rx = 0; rx < 3; rx++) {
                    u64 iv2[4];
                    #pragma unroll
                    for (int p = 0; p < 4; p++) PACKDUP(iv2[p], rowv[p + rx]);
                    const u64* wp = (const u64*)&w_s[buf][cc * 9 + ry * 3 + rx][0];
                    #pragma unroll
                    for (int q = 0; q < OCB / 2; q++) {
                        u64 w2 = wp[q];
                        #pragma unroll
                        for (int p = 0; p < 4; p++)
                            FMA2(acc[q][p], w2, iv2[p], acc[q][p]);
                    }
                }
            }
        }
        buf ^= 1;
    }

    const int gy = by + ly;
    const int gx = bx + lx * 4;
    #pragma unroll
    for (int q = 0; q < OCB / 2; q++) {
        float lo[4], hi[4];
        #pragma unroll
        for (int p = 0; p < 4; p++) {
            unsigned int ul, uh;
            UNPACK2(ul, uh, acc[q][p]);
            lo[p] = __uint_as_float(ul);
            hi[p] = __uint_as_float(uh);
        }
        #pragma unroll
        for (int h = 0; h < 2; h++) {
            int oc = 2 * q + h;
            if (oc0 + oc < Cout) {
                float bvv = bias[oc0 + oc];
                const float* s = h ? hi : lo;
                float v0 = s[0] + bvv, v1 = s[1] + bvv;
                float v2 = s[2] + bvv, v3 = s[3] + bvv;
                if (RELU) { v0 = lrelu(v0); v1 = lrelu(v1); v2 = lrelu(v2); v3 = lrelu(v3); }
                *(float4*)&y[((b * Cout + oc0 + oc) * HH + gy) * WW + gx] =
                    make_float4(v0, v1, v2, v3);
            }
        }
    }
}

// ---------------------------------------------------------------------------
// Offset conv variant: 2 px x 8 oc per thread, 256 threads per block.
// Same 32x16 tile; doubles thread-level parallelism for the
// parallelism-starved 18-channel offset convs (no RELU).
// ---------------------------------------------------------------------------
template<int CIN>
__global__ __launch_bounds__(256, 5)
void conv3x3_off_kernel(const float* __restrict__ x, const float* __restrict__ wt,
                        const float* __restrict__ bias, float* __restrict__ y,
                        int Cout, int OP, int n_ocb)
{
    constexpr int OCB = 8;
    __shared__ float w_s[2][36][OCB];
    __shared__ __align__(16) float in_s[2][4][18][40];

    const int t   = threadIdx.x;
    const int lx  = t & 15;              // 0..15 -> 2 px each
    const int ly  = t >> 4;              // 0..15
    const int bx  = blockIdx.x * 32;
    const int by  = blockIdx.y * 16;
    const int b   = blockIdx.z / n_ocb;
    const int ocb = blockIdx.z % n_ocb;
    const int oc0 = ocb * OCB;

    const float* xb = x + b * CIN * HH * WW;

    u64 acc[OCB / 2][2];
    #pragma unroll
    for (int q = 0; q < OCB / 2; q++) { acc[q][0] = 0ull; acc[q][1] = 0ull; }

    auto load_chunk = [&](int c0, int bi) {
        const float* xc = xb + c0 * HH * WW;
        for (int i = t; i < 4 * 18 * 8; i += 256) {
            int cc  = i / 144;
            int rem = i - cc * 144;
            int r   = rem >> 3;
            int q   = rem & 7;
            int gy  = by - 1 + r;
            bool ok = (unsigned)gy < (unsigned)HH;
            const float* src = xc + cc * HH * WW + (ok ? gy * WW + bx + q * 4 : 0);
            int sz = ok ? 16 : 0;
            CP_ASYNC16Z(s2u(&in_s[bi][cc][r][4 + q * 4]), src, sz);
        }
        for (int i = t; i < 4 * 18 * 2; i += 256) {
            int cc   = i / 36;
            int rem  = i - cc * 36;
            int r    = rem >> 1;
            int side = rem & 1;
            int gy   = by - 1 + r;
            int gx   = side ? bx + 32 : bx - 1;
            bool ok  = ((unsigned)gy < (unsigned)HH) & ((unsigned)gx < (unsigned)WW);
            const float* src = xc + cc * HH * WW + (ok ? gy * WW + gx : 0);
            int sz = ok ? 4 : 0;
            CP_ASYNC4(s2u(&in_s[bi][cc][r][side ? 36 : 3]), src, sz);
        }
        for (int i = t; i < 36 * (OCB / 4); i += 256) {
            int row = i / (OCB / 4);
            int q   = i - row * (OCB / 4);
            CP_ASYNC16(s2u(&w_s[bi][row][q * 4]),
                       &wt[(c0 * 9 + row) * OP + oc0 + q * 4]);
        }
    };

    load_chunk(0, 0);
    CP_COMMIT();

    int buf = 0;
    for (int c0 = 0; c0 < CIN; c0 += 4) {
        CP_WAIT0();
        __syncthreads();
        if (c0 + 4 < CIN) { load_chunk(c0 + 4, buf ^ 1); CP_COMMIT(); }

        #pragma unroll
        for (int cc = 0; cc < 4; cc++) {
            #pragma unroll
            for (int ry = 0; ry < 3; ry++) {
                // window cols lx*2+3 .. lx*2+6: scalar + aligned float2 + scalar
                float e0 = in_s[buf][cc][ly + ry][lx * 2 + 3];
                float2 rm = *(const float2*)&in_s[buf][cc][ly + ry][lx * 2 + 4];
                float e3 = in_s[buf][cc][ly + ry][lx * 2 + 6];
                float rowv[4] = {e0, rm.x, rm.y, e3};
                #pragma unroll
                for (int rx = 0; rx < 3; rx++) {
                    u64 iv2[2];
                    PACKDUP(iv2[0], rowv[rx]);
                    PACKDUP(iv2[1], rowv[rx + 1]);
                    const u64* wp = (const u64*)&w_s[buf][cc * 9 + ry * 3 + rx][0];
                    #pragma unroll
                    for (int q = 0; q < OCB / 2; q++) {
                        u64 w2 = wp[q];
                        FMA2(acc[q][0], w2, iv2[0], acc[q][0]);
                        FMA2(acc[q][1], w2, iv2[1], acc[q][1]);
                    }
                }
            }
        }
        buf ^= 1;
    }

    const int gy = by + ly;
    const int gx = bx + lx * 2;
    #pragma unroll
    for (int q = 0; q < OCB / 2; q++) {
        float lo[2], hi[2];
        #pragma unroll
        for (int p = 0; p < 2; p++) {
            unsigned int ul, uh;
            UNPACK2(ul, uh, acc[q][p]);
            lo[p] = __uint_as_float(ul);
            hi[p] = __uint_as_float(uh);
        }
        #pragma unroll
        for (int h = 0; h < 2; h++) {
            int oc = 2 * q + h;
            if (oc0 + oc < Cout) {
                float bvv = bias[oc0 + oc];
                const float* s = h ? hi : lo;
                float2 r2 = make_float2(s[0] + bvv, s[1] + bvv);
                *(float2*)&y[((b * Cout + oc0 + oc) * HH + gy) * WW + gx] = r2;
            }
        }
    }
}

// ---------------------------------------------------------------------------
// Deformable 3x3 conv + LeakyReLU (exact R10 measured-best form: 433us).
// 256 threads, 64 px on one row, all O channels. CC=4 chunks,
// double-buffered val + weights (cp.async), one barrier per chunk.
// Taps recomputed per chunk from offsets; phase A gathers all 4 channels
// per (k,px) with one address calc. smem 55.3KB + regs<=64 -> 4 CTAs/SM.
// ---------------------------------------------------------------------------
template<int C, int O>
__global__ __launch_bounds__(256, 4)
void dconv3x3_kernel(const float* __restrict__ x, const float* __restrict__ off,
                     const float* __restrict__ wt, const float* __restrict__ bias,
                     float* __restrict__ y)
{
    constexpr int CC = 4;
    constexpr int PX = 64;
    constexpr int KS = CC * 9;          // 36
    constexpr int NC = C / CC;
    constexpr int OT = O / 16;          // 8 (O=128) or 4 (O=64)
    constexpr int HS = HH * WW;
    extern __shared__ __align__(16) float dsm[];
    float* val_s = dsm;                 // 2 * KS * PX
    float* w_s   = dsm + 2 * KS * PX;   // 2 * KS * O

    const int t  = threadIdx.x;
    const int og = t >> 4;               // 0..15
    const int pg = t & 15;               // 0..15 (px base = pg*4)
    const int x0 = blockIdx.x * PX;
    const int yy = blockIdx.y;
    const int b  = blockIdx.z;

    const float* xb  = x + b * C * HS;
    const float* ofb = off + (b * 18 * HH + yy) * WW + x0;

    auto load_w = [&](int ci, int bi) {
        const float4* src = (const float4*)(wt + ci * KS * O);
        float* dst = w_s + bi * KS * O;
        for (int i = t; i < KS * O / 4; i += 256)
            CP_ASYNC16(s2u(dst + i * 4), src + i);
    };

    auto phaseA = [&](int ci, int bi) {
        float* dst = val_s + bi * KS * PX;
        const float* xc = xb + ci * CC * HS;
        #pragma unroll 1
        for (int j = t; j < 9 * PX; j += 256) {
            int px = j & (PX - 1);
            int k  = j >> 6;
            float dy = ofb[(2 * k) * HS + px];
            float dx = ofb[(2 * k + 1) * HS + px];
            int ky = k / 3;
            int kx = k - ky * 3;
            float py  = (float)(yy + ky - 1) + dy;
            float pxx = (float)(x0 + px + kx - 1) + dx;
            float fy = floorf(py), fx = floorf(pxx);
            int yi = (int)fy, xi = (int)fx;
            float wyv = py - fy, wxv = pxx - fx;
            bool y0in = (unsigned)yi < (unsigned)HH;
            bool y1in = (unsigned)(yi + 1) < (unsigned)HH;
            bool x0in = (unsigned)xi < (unsigned)WW;
            bool x1in = (unsigned)(xi + 1) < (unsigned)WW;
            bool ok00 = y0in & x0in, ok01 = y0in & x1in;
            bool ok10 = y1in & x0in, ok11 = y1in & x1in;
            int base = yi * WW + xi;
            float a00[CC], a01[CC], a10[CC], a11[CC];
            #pragma unroll
            for (int cc = 0; cc < CC; cc++) {
                const float* p = xc + cc * HS + base;
                a00[cc] = ok00 ? p[0]      : 0.f;
                a01[cc] = ok01 ? p[1]      : 0.f;
                a10[cc] = ok10 ? p[WW]     : 0.f;
                a11[cc] = ok11 ? p[WW + 1] : 0.f;
            }
            float* d0 = dst + k * PX + px;
            #pragma unroll
            for (int cc = 0; cc < CC; cc++) {
                float v0 = a00[cc] + (a01[cc] - a00[cc]) * wxv;
                float v1 = a10[cc] + (a11[cc] - a10[cc]) * wxv;
                d0[cc * 9 * PX] = v0 + (v1 - v0) * wyv;
            }
        }
    };

    u64 acc[OT / 2][4];
    #pragma unroll
    for (int q = 0; q < OT / 2; q++)
        #pragma unroll
        for (int p = 0; p < 4; p++) acc[q][p] = 0ull;

    // prologue
    load_w(0, 0);
    CP_COMMIT();
    phaseA(0, 0);

    for (int i = 0; i < NC; i++) {
        CP_WAIT0();
        __syncthreads();      // val(i), w(i) visible; prior buffers free
        if (i + 1 < NC) { load_w(i + 1, (i + 1) & 1); CP_COMMIT(); }

        // phase B(i)
        const float* vb = val_s + (i & 1) * KS * PX;
        const float* wb = w_s + (i & 1) * KS * O;
        #pragma unroll 4
        for (int kk = 0; kk < KS; kk++) {
            float4 v4 = *(const float4*)&vb[kk * PX + pg * 4];
            u64 vv[4];
            PACKDUP(vv[0], v4.x);
            PACKDUP(vv[1], v4.y);
            PACKDUP(vv[2], v4.z);
            PACKDUP(vv[3], v4.w);
            const ulonglong2* wp2 = (const ulonglong2*)&wb[kk * O + og * OT];
            #pragma unroll
            for (int q2 = 0; q2 < OT / 4; q2++) {
                ulonglong2 ww = wp2[q2];
                #pragma unroll
                for (int p = 0; p < 4; p++)
                    FMA2(acc[2 * q2][p], ww.x, vv[p], acc[2 * q2][p]);
                #pragma unroll
                for (int p = 0; p < 4; p++)
                    FMA2(acc[2 * q2 + 1][p], ww.y, vv[p], acc[2 * q2 + 1][p]);
            }
        }

        // phase A(i+1)
        if (i + 1 < NC) phaseA(i + 1, (i + 1) & 1);
    }

    const int gx = x0 + pg * 4;
    #pragma unroll
    for (int q = 0; q < OT / 2; q++) {
        float lo[4], hi[4];
        #pragma unroll
        for (int p = 0; p < 4; p++) {
            unsigned int ul, uh;
            UNPACK2(ul, uh, acc[q][p]);
            lo[p] = __uint_as_float(ul);
            hi[p] = __uint_as_float(uh);
        }
        #pragma unroll
        for (int h = 0; h < 2; h++) {
            int o = og * OT + 2 * q + h;
            float bvv = bias[o];
            const float* s = h ? hi : lo;
            float4 r4;
            r4.x = lrelu(s[0] + bvv);
            r4.y = lrelu(s[1] + bvv);
            r4.z = lrelu(s[2] + bvv);
            r4.w = lrelu(s[3] + bvv);
            *(float4*)&y[((b * O + o) * HH + yy) * WW + gx] = r4;
        }
    }
}

// ---------------------------------------------------------------------------
// Launch: one prep kernel (all 9 weight transposes), then 3 stages of
// conv(+leaky) -> offset conv -> deform conv(+leaky). Graph-capturable.
// ---------------------------------------------------------------------------
extern "C" void kernel_launch(void* const* d_in, const int* in_sizes, int n_in,
                              void* d_out, int out_size)
{
    const float* x = (const float*)d_in[0];
    const float* p[18];
    for (int i = 0; i < 18; i++) p[i] = (const float*)d_in[1 + i];

    float *A, *Bf, *OFF;
    float (*WTC)[128 * 9 * 128], (*WTO)[128 * 9 * 24], (*WTD)[128 * 9 * 128];
    cudaGetSymbolAddress((void**)&A,   g_A);
    cudaGetSymbolAddress((void**)&Bf,  g_B);
    cudaGetSymbolAddress((void**)&OFF, g_off);
    cudaGetSymbolAddress((void**)&WTC, g_wtc);
    cudaGetSymbolAddress((void**)&WTO, g_wto);
    cudaGetSymbolAddress((void**)&WTD, g_wtd);

    // ---- prep: all weight transposes in one launch ----
    PrepJobs jobs;
    const int cin_s[3]  = {64, 128, 128};
    const int cout_s[3] = {128, 128, 64};
    for (int s = 0; s < 3; s++) {
        jobs.src[3 * s + 0] = p[6 * s + 0];
        jobs.dst[3 * s + 0] = WTC[s];
        jobs.C9[3 * s + 0] = cin_s[s] * 9;
        jobs.O[3 * s + 0] = cout_s[s];
        jobs.OP[3 * s + 0] = cout_s[s];
        jobs.src[3 * s + 1] = p[6 * s + 2];
        jobs.dst[3 * s + 1] = WTO[s];
        jobs.C9[3 * s + 1] = cout_s[s] * 9;
        jobs.O[3 * s + 1] = 18;
        jobs.OP[3 * s + 1] = 24;
        jobs.src[3 * s + 2] = p[6 * s + 4];
        jobs.dst[3 * s + 2] = WTD[s];
        jobs.C9[3 * s + 2] = cout_s[s] * 9;
        jobs.O[3 * s + 2] = cout_s[s];
        jobs.OP[3 * s + 2] = cout_s[s];
    }
    prep_kernel<<<dim3(64, 9), 256>>>(jobs);

    // dconv smem: val(2*36*64) + w(2*36*O) floats
    const int smemD128 = (2 * 36 * 64 + 2 * 36 * 128) * 4;  // 55296
    const int smemD64  = (2 * 36 * 64 + 2 * 36 * 64) * 4;   // 36864
    cudaFuncSetAttribute(dconv3x3_kernel<128, 128>,
                         cudaFuncAttributeMaxDynamicSharedMemorySize, smemD128);
    cudaFuncSetAttribute(dconv3x3_kernel<64, 64>,
                         cudaFuncAttributeMaxDynamicSharedMemorySize, smemD64);

    dim3 blk128(128), blk256(256);
    dim3 dgrid(WW / 64, HH, BB);

    // ---- stage 1: 64 -> 128 ----
    conv3x3_kernel<64, 16, true><<<dim3(4, 8, BB * 8), blk128>>>(x, WTC[0], p[1], A, 128, 128, 8);
    conv3x3_off_kernel<128><<<dim3(4, 8, BB * 3), blk256>>>(A, WTO[0], p[3], OFF, 18, 24, 3);
    dconv3x3_kernel<128, 128><<<dgrid, blk256, smemD128>>>(A, OFF, WTD[0], p[5], Bf);

    // ---- stage 2: 128 -> 128 ----
    conv3x3_kernel<128, 16, true><<<dim3(4, 8, BB * 8), blk128>>>(Bf, WTC[1], p[7], A, 128, 128, 8);
    conv3x3_off_kernel<128><<<dim3(4, 8, BB * 3), blk256>>>(A, WTO[1], p[9], OFF, 18, 24, 3);
    dconv3x3_kernel<128, 128><<<dgrid, blk256, smemD128>>>(A, OFF, WTD[1], p[11], Bf);

    // ---- stage 3: 128 -> 64 ----
    conv3x3_kernel<128, 16, true><<<dim3(4, 8, BB * 4), blk128>>>(Bf, WTC[2], p[13], A, 64, 64, 4);
    conv3x3_off_kernel<64><<<dim3(4, 8, BB * 3), blk256>>>(A, WTO[2], p[15], OFF, 18, 24, 3);
    dconv3x3_kernel<64, 64><<<dgrid, blk256, smemD64>>>(A, OFF, WTD[2], p[17], (float*)d_out);
}

// round 15
// speedup vs baseline: 1.0558x; 1.0558x over previous
#include <cuda_runtime.h>
#include <math.h>

// Problem constants (fixed by reference: x = (4, 64, 128, 128) fp32)
#define HH 128
#define WW 128
#define BB 4

// Scratch (allocation-free: __device__ globals)
__device__ float g_A[BB * 128 * HH * WW];        // 32 MB ping
__device__ float g_B[BB * 128 * HH * WW];        // 32 MB pong
__device__ float g_off[BB * 18 * HH * WW];       // offsets
__device__ float g_wtc[3][128 * 9 * 128];        // per-stage transposed conv weights
__device__ float g_wto[3][128 * 9 * 24];         // per-stage transposed offset weights
__device__ float g_wtd[3][128 * 9 * 128];        // per-stage transposed deform weights

typedef unsigned long long u64;

// Packed fp32x2 ops (Blackwell FFMA2 — only reachable via PTX)
#define FMA2(d, a, b, c) \
    asm("fma.rn.f32x2 %0, %1, %2, %3;" : "=l"(d) : "l"(a), "l"(b), "l"(c))
#define PACKDUP(out, f) \
    asm("mov.b64 %0, {%1, %1};" : "=l"(out) : "r"(__float_as_uint(f)))
#define UNPACK2(lo, hi, in) \
    asm("mov.b64 {%0, %1}, %2;" : "=r"(lo), "=r"(hi) : "l"(in))

// cp.async (LDGSTS)
#define CP_ASYNC4(dst_s, src_g, szr) \
    asm volatile("cp.async.ca.shared.global [%0], [%1], 4, %2;" \
                 :: "r"(dst_s), "l"(src_g), "r"(szr))
#define CP_ASYNC16(dst_s, src_g) \
    asm volatile("cp.async.ca.shared.global [%0], [%1], 16;" \
                 :: "r"(dst_s), "l"(src_g))
#define CP_ASYNC16Z(dst_s, src_g, szr) \
    asm volatile("cp.async.ca.shared.global [%0], [%1], 16, %2;" \
                 :: "r"(dst_s), "l"(src_g), "r"(szr))
#define CP_COMMIT() asm volatile("cp.async.commit_group;")
#define CP_WAIT0()  asm volatile("cp.async.wait_group 0;")

__device__ __forceinline__ unsigned s2u(const void* p) {
    return (unsigned)__cvta_generic_to_shared(p);
}
__device__ __forceinline__ float lrelu(float v) { return v >= 0.f ? v : 0.2f * v; }

// ---------------------------------------------------------------------------
// One prep kernel does ALL 9 weight transposes (they depend only on inputs).
// ---------------------------------------------------------------------------
struct PrepJobs {
    const float* src[9];
    float*       dst[9];
    int C9[9], O[9], OP[9];
};

__global__ void prep_kernel(PrepJobs jobs)
{
    int job = blockIdx.y;
    int C9 = jobs.C9[job], O = jobs.O[job], OP = jobs.OP[job];
    int n = C9 * OP;
    const float* src = jobs.src[job];
    float* dst = jobs.dst[job];
    for (int idx = blockIdx.x * 256 + threadIdx.x; idx < n; idx += gridDim.x * 256) {
        int j = idx / OP;
        int o = idx - j * OP;
        dst[idx] = (o < O) ? src[o * C9 + j] : 0.f;
    }
}

// ---------------------------------------------------------------------------
// Plain 3x3 conv (R10 measured-best form — untouched).
// ---------------------------------------------------------------------------
template<int CIN, int OCB, bool RELU>
__global__ __launch_bounds__(128, 5)
void conv3x3_kernel(const float* __restrict__ x, const float* __restrict__ wt,
                    const float* __restrict__ bias, float* __restrict__ y,
                    int Cout, int OP, int n_ocb)
{
    __shared__ float w_s[2][36][OCB];
    __shared__ __align__(16) float in_s[2][4][18][40];
    // layout per row: col 3 = gx bx-1, cols 4..35 = bx..bx+31, col 36 = bx+32

    const int t   = threadIdx.x;
    const int lx  = t & 7;
    const int ly  = t >> 3;
    const int bx  = blockIdx.x * 32;
    const int by  = blockIdx.y * 16;
    const int b   = blockIdx.z / n_ocb;
    const int ocb = blockIdx.z % n_ocb;
    const int oc0 = ocb * OCB;

    const float* xb = x + b * CIN * HH * WW;

    u64 acc[OCB / 2][4];
    #pragma unroll
    for (int q = 0; q < OCB / 2; q++)
        #pragma unroll
        for (int p = 0; p < 4; p++) acc[q][p] = 0ull;

    auto load_chunk = [&](int c0, int bi) {
        const float* xc = xb + c0 * HH * WW;
        for (int i = t; i < 4 * 18 * 8; i += 128) {
            int cc  = i / 144;
            int rem = i - cc * 144;
            int r   = rem >> 3;
            int q   = rem & 7;
            int gy  = by - 1 + r;
            bool ok = (unsigned)gy < (unsigned)HH;
            const float* src = xc + cc * HH * WW + (ok ? gy * WW + bx + q * 4 : 0);
            int sz = ok ? 16 : 0;
            CP_ASYNC16Z(s2u(&in_s[bi][cc][r][4 + q * 4]), src, sz);
        }
        for (int i = t; i < 4 * 18 * 2; i += 128) {
            int cc   = i / 36;
            int rem  = i - cc * 36;
            int r    = rem >> 1;
            int side = rem & 1;
            int gy   = by - 1 + r;
            int gx   = side ? bx + 32 : bx - 1;
            bool ok  = ((unsigned)gy < (unsigned)HH) & ((unsigned)gx < (unsigned)WW);
            const float* src = xc + cc * HH * WW + (ok ? gy * WW + gx : 0);
            int sz = ok ? 4 : 0;
            CP_ASYNC4(s2u(&in_s[bi][cc][r][side ? 36 : 3]), src, sz);
        }
        for (int i = t; i < 36 * (OCB / 4); i += 128) {
            int row = i / (OCB / 4);
            int q   = i - row * (OCB / 4);
            CP_ASYNC16(s2u(&w_s[bi][row][q * 4]),
                       &wt[(c0 * 9 + row) * OP + oc0 + q * 4]);
        }
    };

    load_chunk(0, 0);
    CP_COMMIT();

    int buf = 0;
    for (int c0 = 0; c0 < CIN; c0 += 4) {
        CP_WAIT0();
        __syncthreads();
        if (c0 + 4 < CIN) { load_chunk(c0 + 4, buf ^ 1); CP_COMMIT(); }

        #pragma unroll
        for (int cc = 0; cc < 4; cc++) {
            #pragma unroll
            for (int ry = 0; ry < 3; ry++) {
                float e0 = in_s[buf][cc][ly + ry][lx * 4 + 3];
                float4 rm = *(const float4*)&in_s[buf][cc][ly + ry][lx * 4 + 4];
                float e5 = in_s[buf][cc][ly + ry][lx * 4 + 8];
                float rowv[6] = {e0, rm.x, rm.y, rm.z, rm.w, e5};
                #pragma unroll
                for (int rx = 0; rx < 3; rx++) {
                    u64 iv2[4];
                    #pragma unroll
                    for (int p = 0; p < 4; p++) PACKDUP(iv2[p], rowv[p + rx]);
                    const u64* wp = (const u64*)&w_s[buf][cc * 9 + ry * 3 + rx][0];
                    #pragma unroll
                    for (int q = 0; q < OCB / 2; q++) {
                        u64 w2 = wp[q];
                        #pragma unroll
                        for (int p = 0; p < 4; p++)
                            FMA2(acc[q][p], w2, iv2[p], acc[q][p]);
                    }
                }
            }
        }
        buf ^= 1;
    }

    const int gy = by + ly;
    const int gx = bx + lx * 4;
    #pragma unroll
    for (int q = 0; q < OCB / 2; q++) {
        float lo[4], hi[4];
        #pragma unroll
        for (int p = 0; p < 4; p++) {
            unsigned int ul, uh;
            UNPACK2(ul, uh, acc[q][p]);
            lo[p] = __uint_as_float(ul);
            hi[p] = __uint_as_float(uh);
        }
        #pragma unroll
        for (int h = 0; h < 2; h++) {
            int oc = 2 * q + h;
            if (oc0 + oc < Cout) {
                float bvv = bias[oc0 + oc];
                const float* s = h ? hi : lo;
                float v0 = s[0] + bvv, v1 = s[1] + bvv;
                float v2 = s[2] + bvv, v3 = s[3] + bvv;
                if (RELU) { v0 = lrelu(v0); v1 = lrelu(v1); v2 = lrelu(v2); v3 = lrelu(v3); }
                *(float4*)&y[((b * Cout + oc0 + oc) * HH + gy) * WW + gx] =
                    make_float4(v0, v1, v2, v3);
            }
        }
    }
}

// ---------------------------------------------------------------------------
// Offset conv variant: 2 px x 8 oc per thread, 256 threads per block.
// __launch_bounds__(256, 3): reg budget 85/thread (no spills — the
// R13 (256,5) variant capped regs at 51 and spilled). 24 warps/SM.
// ---------------------------------------------------------------------------
template<int CIN>
__global__ __launch_bounds__(256, 3)
void conv3x3_off_kernel(const float* __restrict__ x, const float* __restrict__ wt,
                        const float* __restrict__ bias, float* __restrict__ y,
                        int Cout, int OP, int n_ocb)
{
    constexpr int OCB = 8;
    __shared__ float w_s[2][36][OCB];
    __shared__ __align__(16) float in_s[2][4][18][40];

    const int t   = threadIdx.x;
    const int lx  = t & 15;              // 0..15 -> 2 px each
    const int ly  = t >> 4;              // 0..15
    const int bx  = blockIdx.x * 32;
    const int by  = blockIdx.y * 16;
    const int b   = blockIdx.z / n_ocb;
    const int ocb = blockIdx.z % n_ocb;
    const int oc0 = ocb * OCB;

    const float* xb = x + b * CIN * HH * WW;

    u64 acc[OCB / 2][2];
    #pragma unroll
    for (int q = 0; q < OCB / 2; q++) { acc[q][0] = 0ull; acc[q][1] = 0ull; }

    auto load_chunk = [&](int c0, int bi) {
        const float* xc = xb + c0 * HH * WW;
        for (int i = t; i < 4 * 18 * 8; i += 256) {
            int cc  = i / 144;
            int rem = i - cc * 144;
            int r   = rem >> 3;
            int q   = rem & 7;
            int gy  = by - 1 + r;
            bool ok = (unsigned)gy < (unsigned)HH;
            const float* src = xc + cc * HH * WW + (ok ? gy * WW + bx + q * 4 : 0);
            int sz = ok ? 16 : 0;
            CP_ASYNC16Z(s2u(&in_s[bi][cc][r][4 + q * 4]), src, sz);
        }
        for (int i = t; i < 4 * 18 * 2; i += 256) {
            int cc   = i / 36;
            int rem  = i - cc * 36;
            int r    = rem >> 1;
            int side = rem & 1;
            int gy   = by - 1 + r;
            int gx   = side ? bx + 32 : bx - 1;
            bool ok  = ((unsigned)gy < (unsigned)HH) & ((unsigned)gx < (unsigned)WW);
            const float* src = xc + cc * HH * WW + (ok ? gy * WW + gx : 0);
            int sz = ok ? 4 : 0;
            CP_ASYNC4(s2u(&in_s[bi][cc][r][side ? 36 : 3]), src, sz);
        }
        for (int i = t; i < 36 * (OCB / 4); i += 256) {
            int row = i / (OCB / 4);
            int q   = i - row * (OCB / 4);
            CP_ASYNC16(s2u(&w_s[bi][row][q * 4]),
                       &wt[(c0 * 9 + row) * OP + oc0 + q * 4]);
        }
    };

    load_chunk(0, 0);
    CP_COMMIT();

    int buf = 0;
    for (int c0 = 0; c0 < CIN; c0 += 4) {
        CP_WAIT0();
        __syncthreads();
        if (c0 + 4 < CIN) { load_chunk(c0 + 4, buf ^ 1); CP_COMMIT(); }

        #pragma unroll
        for (int cc = 0; cc < 4; cc++) {
            #pragma unroll
            for (int ry = 0; ry < 3; ry++) {
                // window cols lx*2+3 .. lx*2+6: scalar + aligned float2 + scalar
                float e0 = in_s[buf][cc][ly + ry][lx * 2 + 3];
                float2 rm = *(const float2*)&in_s[buf][cc][ly + ry][lx * 2 + 4];
                float e3 = in_s[buf][cc][ly + ry][lx * 2 + 6];
                float rowv[4] = {e0, rm.x, rm.y, e3};
                #pragma unroll
                for (int rx = 0; rx < 3; rx++) {
                    u64 iv2[2];
                    PACKDUP(iv2[0], rowv[rx]);
                    PACKDUP(iv2[1], rowv[rx + 1]);
                    const u64* wp = (const u64*)&w_s[buf][cc * 9 + ry * 3 + rx][0];
                    #pragma unroll
                    for (int q = 0; q < OCB / 2; q++) {
                        u64 w2 = wp[q];
                        FMA2(acc[q][0], w2, iv2[0], acc[q][0]);
                        FMA2(acc[q][1], w2, iv2[1], acc[q][1]);
                    }
                }
            }
        }
        buf ^= 1;
    }

    const int gy = by + ly;
    const int gx = bx + lx * 2;
    #pragma unroll
    for (int q = 0; q < OCB / 2; q++) {
        float lo[2], hi[2];
        #pragma unroll
        for (int p = 0; p < 2; p++) {
            unsigned int ul, uh;
            UNPACK2(ul, uh, acc[q][p]);
            lo[p] = __uint_as_float(ul);
            hi[p] = __uint_as_float(uh);
        }
        #pragma unroll
        for (int h = 0; h < 2; h++) {
            int oc = 2 * q + h;
            if (oc0 + oc < Cout) {
                float bvv = bias[oc0 + oc];
                const float* s = h ? hi : lo;
                float2 r2 = make_float2(s[0] + bvv, s[1] + bvv);
                *(float2*)&y[((b * Cout + oc0 + oc) * HH + gy) * WW + gx] = r2;
            }
        }
    }
}

// ---------------------------------------------------------------------------
// Deformable 3x3 conv + LeakyReLU (exact R10 measured-best form: 433us).
// 256 threads, 64 px on one row, all O channels. CC=4 chunks,
// double-buffered val + weights (cp.async), one barrier per chunk.
// ---------------------------------------------------------------------------
template<int C, int O>
__global__ __launch_bounds__(256, 4)
void dconv3x3_kernel(const float* __restrict__ x, const float* __restrict__ off,
                     const float* __restrict__ wt, const float* __restrict__ bias,
                     float* __restrict__ y)
{
    constexpr int CC = 4;
    constexpr int PX = 64;
    constexpr int KS = CC * 9;          // 36
    constexpr int NC = C / CC;
    constexpr int OT = O / 16;          // 8 (O=128) or 4 (O=64)
    constexpr int HS = HH * WW;
    extern __shared__ __align__(16) float dsm[];
    float* val_s = dsm;                 // 2 * KS * PX
    float* w_s   = dsm + 2 * KS * PX;   // 2 * KS * O

    const int t  = threadIdx.x;
    const int og = t >> 4;               // 0..15
    const int pg = t & 15;               // 0..15 (px base = pg*4)
    const int x0 = blockIdx.x * PX;
    const int yy = blockIdx.y;
    const int b  = blockIdx.z;

    const float* xb  = x + b * C * HS;
    const float* ofb = off + (b * 18 * HH + yy) * WW + x0;

    auto load_w = [&](int ci, int bi) {
        const float4* src = (const float4*)(wt + ci * KS * O);
        float* dst = w_s + bi * KS * O;
        for (int i = t; i < KS * O / 4; i += 256)
            CP_ASYNC16(s2u(dst + i * 4), src + i);
    };

    auto phaseA = [&](int ci, int bi) {
        float* dst = val_s + bi * KS * PX;
        const float* xc = xb + ci * CC * HS;
        #pragma unroll 1
        for (int j = t; j < 9 * PX; j += 256) {
            int px = j & (PX - 1);
            int k  = j >> 6;
            float dy = ofb[(2 * k) * HS + px];
            float dx = ofb[(2 * k + 1) * HS + px];
            int ky = k / 3;
            int kx = k - ky * 3;
            float py  = (float)(yy + ky - 1) + dy;
            float pxx = (float)(x0 + px + kx - 1) + dx;
            float fy = floorf(py), fx = floorf(pxx);
            int yi = (int)fy, xi = (int)fx;
            float wyv = py - fy, wxv = pxx - fx;
            bool y0in = (unsigned)yi < (unsigned)HH;
            bool y1in = (unsigned)(yi + 1) < (unsigned)HH;
            bool x0in = (unsigned)xi < (unsigned)WW;
            bool x1in = (unsigned)(xi + 1) < (unsigned)WW;
            bool ok00 = y0in & x0in, ok01 = y0in & x1in;
            bool ok10 = y1in & x0in, ok11 = y1in & x1in;
            int base = yi * WW + xi;
            float a00[CC], a01[CC], a10[CC], a11[CC];
            #pragma unroll
            for (int cc = 0; cc < CC; cc++) {
                const float* p = xc + cc * HS + base;
                a00[cc] = ok00 ? p[0]      : 0.f;
                a01[cc] = ok01 ? p[1]      : 0.f;
                a10[cc] = ok10 ? p[WW]     : 0.f;
                a11[cc] = ok11 ? p[WW + 1] : 0.f;
            }
            float* d0 = dst + k * PX + px;
            #pragma unroll
            for (int cc = 0; cc < CC; cc++) {
                float v0 = a00[cc] + (a01[cc] - a00[cc]) * wxv;
                float v1 = a10[cc] + (a11[cc] - a10[cc]) * wxv;
                d0[cc * 9 * PX] = v0 + (v1 - v0) * wyv;
            }
        }
    };

    u64 acc[OT / 2][4];
    #pragma unroll
    for (int q = 0; q < OT / 2; q++)
        #pragma unroll
        for (int p = 0; p < 4; p++) acc[q][p] = 0ull;

    // prologue
    load_w(0, 0);
    CP_COMMIT();
    phaseA(0, 0);

    for (int i = 0; i < NC; i++) {
        CP_WAIT0();
        __syncthreads();      // val(i), w(i) visible; prior buffers free
        if (i + 1 < NC) { load_w(i + 1, (i + 1) & 1); CP_COMMIT(); }

        // phase B(i)
        const float* vb = val_s + (i & 1) * KS * PX;
        const float* wb = w_s + (i & 1) * KS * O;
        #pragma unroll 4
        for (int kk = 0; kk < KS; kk++) {
            float4 v4 = *(const float4*)&vb[kk * PX + pg * 4];
            u64 vv[4];
            PACKDUP(vv[0], v4.x);
            PACKDUP(vv[1], v4.y);
            PACKDUP(vv[2], v4.z);
            PACKDUP(vv[3], v4.w);
            const ulonglong2* wp2 = (const ulonglong2*)&wb[kk * O + og * OT];
            #pragma unroll
            for (int q2 = 0; q2 < OT / 4; q2++) {
                ulonglong2 ww = wp2[q2];
                #pragma unroll
                for (int p = 0; p < 4; p++)
                    FMA2(acc[2 * q2][p], ww.x, vv[p], acc[2 * q2][p]);
                #pragma unroll
                for (int p = 0; p < 4; p++)
                    FMA2(acc[2 * q2 + 1][p], ww.y, vv[p], acc[2 * q2 + 1][p]);
            }
        }

        // phase A(i+1)
        if (i + 1 < NC) phaseA(i + 1, (i + 1) & 1);
    }

    const int gx = x0 + pg * 4;
    #pragma unroll
    for (int q = 0; q < OT / 2; q++) {
        float lo[4], hi[4];
        #pragma unroll
        for (int p = 0; p < 4; p++) {
            unsigned int ul, uh;
            UNPACK2(ul, uh, acc[q][p]);
            lo[p] = __uint_as_float(ul);
            hi[p] = __uint_as_float(uh);
        }
        #pragma unroll
        for (int h = 0; h < 2; h++) {
            int o = og * OT + 2 * q + h;
            float bvv = bias[o];
            const float* s = h ? hi : lo;
            float4 r4;
            r4.x = lrelu(s[0] + bvv);
            r4.y = lrelu(s[1] + bvv);
            r4.z = lrelu(s[2] + bvv);
            r4.w = lrelu(s[3] + bvv);
            *(float4*)&y[((b * O + o) * HH + yy) * WW + gx] = r4;
        }
    }
}

// ---------------------------------------------------------------------------
// Launch: one prep kernel (all 9 weight transposes), then 3 stages of
// conv(+leaky) -> offset conv -> deform conv(+leaky). Graph-capturable.
// ---------------------------------------------------------------------------
extern "C" void kernel_launch(void* const* d_in, const int* in_sizes, int n_in,
                              void* d_out, int out_size)
{
    const float* x = (const float*)d_in[0];
    const float* p[18];
    for (int i = 0; i < 18; i++) p[i] = (const float*)d_in[1 + i];

    float *A, *Bf, *OFF;
    float (*WTC)[128 * 9 * 128], (*WTO)[128 * 9 * 24], (*WTD)[128 * 9 * 128];
    cudaGetSymbolAddress((void**)&A,   g_A);
    cudaGetSymbolAddress((void**)&Bf,  g_B);
    cudaGetSymbolAddress((void**)&OFF, g_off);
    cudaGetSymbolAddress((void**)&WTC, g_wtc);
    cudaGetSymbolAddress((void**)&WTO, g_wto);
    cudaGetSymbolAddress((void**)&WTD, g_wtd);

    // ---- prep: all weight transposes in one launch ----
    PrepJobs jobs;
    const int cin_s[3]  = {64, 128, 128};
    const int cout_s[3] = {128, 128, 64};
    for (int s = 0; s < 3; s++) {
        jobs.src[3 * s + 0] = p[6 * s + 0];
        jobs.dst[3 * s + 0] = WTC[s];
        jobs.C9[3 * s + 0] = cin_s[s] * 9;
        jobs.O[3 * s + 0] = cout_s[s];
        jobs.OP[3 * s + 0] = cout_s[s];
        jobs.src[3 * s + 1] = p[6 * s + 2];
        jobs.dst[3 * s + 1] = WTO[s];
        jobs.C9[3 * s + 1] = cout_s[s] * 9;
        jobs.O[3 * s + 1] = 18;
        jobs.OP[3 * s + 1] = 24;
        jobs.src[3 * s + 2] = p[6 * s + 4];
        jobs.dst[3 * s + 2] = WTD[s];
        jobs.C9[3 * s + 2] = cout_s[s] * 9;
        jobs.O[3 * s + 2] = cout_s[s];
        jobs.OP[3 * s + 2] = cout_s[s];
    }
    prep_kernel<<<dim3(64, 9), 256>>>(jobs);

    // dconv smem: val(2*36*64) + w(2*36*O) floats
    const int smemD128 = (2 * 36 * 64 + 2 * 36 * 128) * 4;  // 55296
    const int smemD64  = (2 * 36 * 64 + 2 * 36 * 64) * 4;   // 36864
    cudaFuncSetAttribute(dconv3x3_kernel<128, 128>,
                         cudaFuncAttributeMaxDynamicSharedMemorySize, smemD128);
    cudaFuncSetAttribute(dconv3x3_kernel<64, 64>,
                         cudaFuncAttributeMaxDynamicSharedMemorySize, smemD64);

    dim3 blk128(128), blk256(256);
    dim3 dgrid(WW / 64, HH, BB);

    // ---- stage 1: 64 -> 128 ----
    conv3x3_kernel<64, 16, true><<<dim3(4, 8, BB * 8), blk128>>>(x, WTC[0], p[1], A, 128, 128, 8);
    conv3x3_off_kernel<128><<<dim3(4, 8, BB * 3), blk256>>>(A, WTO[0], p[3], OFF, 18, 24, 3);
    dconv3x3_kernel<128, 128><<<dgrid, blk256, smemD128>>>(A, OFF, WTD[0], p[5], Bf);

    // ---- stage 2: 128 -> 128 ----
    conv3x3_kernel<128, 16, true><<<dim3(4, 8, BB * 8), blk128>>>(Bf, WTC[1], p[7], A, 128, 128, 8);
    conv3x3_off_kernel<128><<<dim3(4, 8, BB * 3), blk256>>>(A, WTO[1], p[9], OFF, 18, 24, 3);
    dconv3x3_kernel<128, 128><<<dgrid, blk256, smemD128>>>(A, OFF, WTD[1], p[11], Bf);

    // ---- stage 3: 128 -> 64 ----
    conv3x3_kernel<128, 16, true><<<dim3(4, 8, BB * 4), blk128>>>(Bf, WTC[2], p[13], A, 64, 64, 4);
    conv3x3_off_kernel<64><<<dim3(4, 8, BB * 3), blk256>>>(A, WTO[2], p[15], OFF, 18, 24, 3);
    dconv3x3_kernel<64, 64><<<dgrid, blk256, smemD64>>>(A, OFF, WTD[2], p[17], (float*)d_out);
}

// round 16
// speedup vs baseline: 1.0816x; 1.0244x over previous
#include <cuda_runtime.h>
#include <math.h>

// Problem constants (fixed by reference: x = (4, 64, 128, 128) fp32)
#define HH 128
#define WW 128
#define BB 4

// Scratch (allocation-free: __device__ globals)
__device__ float g_A[BB * 128 * HH * WW];        // 32 MB ping
__device__ float g_B[BB * 128 * HH * WW];        // 32 MB pong
__device__ float g_off[BB * 18 * HH * WW];       // offsets
__device__ float g_wtc[3][128 * 9 * 128];        // per-stage transposed conv weights
__device__ float g_wto[3][128 * 9 * 24];         // per-stage transposed offset weights
__device__ float g_wtd[3][128 * 9 * 128];        // per-stage transposed deform weights

typedef unsigned long long u64;

// Packed fp32x2 ops (Blackwell FFMA2 — only reachable via PTX)
#define FMA2(d, a, b, c) \
    asm("fma.rn.f32x2 %0, %1, %2, %3;" : "=l"(d) : "l"(a), "l"(b), "l"(c))
#define PACKDUP(out, f) \
    asm("mov.b64 %0, {%1, %1};" : "=l"(out) : "r"(__float_as_uint(f)))
#define UNPACK2(lo, hi, in) \
    asm("mov.b64 {%0, %1}, %2;" : "=r"(lo), "=r"(hi) : "l"(in))

// cp.async (LDGSTS)
#define CP_ASYNC4(dst_s, src_g, szr) \
    asm volatile("cp.async.ca.shared.global [%0], [%1], 4, %2;" \
                 :: "r"(dst_s), "l"(src_g), "r"(szr))
#define CP_ASYNC16(dst_s, src_g) \
    asm volatile("cp.async.ca.shared.global [%0], [%1], 16;" \
                 :: "r"(dst_s), "l"(src_g))
#define CP_ASYNC16Z(dst_s, src_g, szr) \
    asm volatile("cp.async.ca.shared.global [%0], [%1], 16, %2;" \
                 :: "r"(dst_s), "l"(src_g), "r"(szr))
#define CP_COMMIT() asm volatile("cp.async.commit_group;")
#define CP_WAIT0()  asm volatile("cp.async.wait_group 0;")

__device__ __forceinline__ unsigned s2u(const void* p) {
    return (unsigned)__cvta_generic_to_shared(p);
}
__device__ __forceinline__ float lrelu(float v) { return v >= 0.f ? v : 0.2f * v; }

// ---------------------------------------------------------------------------
// One prep kernel does ALL 9 weight transposes (they depend only on inputs).
// ---------------------------------------------------------------------------
struct PrepJobs {
    const float* src[9];
    float*       dst[9];
    int C9[9], O[9], OP[9];
};

__global__ void prep_kernel(PrepJobs jobs)
{
    int job = blockIdx.y;
    int C9 = jobs.C9[job], O = jobs.O[job], OP = jobs.OP[job];
    int n = C9 * OP;
    const float* src = jobs.src[job];
    float* dst = jobs.dst[job];
    for (int idx = blockIdx.x * 256 + threadIdx.x; idx < n; idx += gridDim.x * 256) {
        int j = idx / OP;
        int o = idx - j * OP;
        dst[idx] = (o < O) ? src[o * C9 + j] : 0.f;
    }
}

// ---------------------------------------------------------------------------
// Plain 3x3 conv, stride 1, pad 1, optional LeakyReLU.
// 32(x) x 16(y) px tile, OCB oc per block, 128 threads, 5 CTAs/SM (reg cap).
// Thread: 4 px x OCB oc as OCB/2 f32x2 pairs.
// R10 form + ONE change: weight pairs read as ulonglong2 (LDS.128,
// broadcast, conflict-free; 4 loads per tap instead of 8 for OCB=16).
// ---------------------------------------------------------------------------
template<int CIN, int OCB, bool RELU>
__global__ __launch_bounds__(128, 5)
void conv3x3_kernel(const float* __restrict__ x, const float* __restrict__ wt,
                    const float* __restrict__ bias, float* __restrict__ y,
                    int Cout, int OP, int n_ocb)
{
    __shared__ __align__(16) float w_s[2][36][OCB];
    __shared__ __align__(16) float in_s[2][4][18][40];
    // layout per row: col 3 = gx bx-1, cols 4..35 = bx..bx+31, col 36 = bx+32

    const int t   = threadIdx.x;
    const int lx  = t & 7;
    const int ly  = t >> 3;
    const int bx  = blockIdx.x * 32;
    const int by  = blockIdx.y * 16;
    const int b   = blockIdx.z / n_ocb;
    const int ocb = blockIdx.z % n_ocb;
    const int oc0 = ocb * OCB;

    const float* xb = x + b * CIN * HH * WW;

    u64 acc[OCB / 2][4];
    #pragma unroll
    for (int q = 0; q < OCB / 2; q++)
        #pragma unroll
        for (int p = 0; p < 4; p++) acc[q][p] = 0ull;

    auto load_chunk = [&](int c0, int bi) {
        const float* xc = xb + c0 * HH * WW;
        for (int i = t; i < 4 * 18 * 8; i += 128) {
            int cc  = i / 144;
            int rem = i - cc * 144;
            int r   = rem >> 3;
            int q   = rem & 7;
            int gy  = by - 1 + r;
            bool ok = (unsigned)gy < (unsigned)HH;
            const float* src = xc + cc * HH * WW + (ok ? gy * WW + bx + q * 4 : 0);
            int sz = ok ? 16 : 0;
            CP_ASYNC16Z(s2u(&in_s[bi][cc][r][4 + q * 4]), src, sz);
        }
        for (int i = t; i < 4 * 18 * 2; i += 128) {
            int cc   = i / 36;
            int rem  = i - cc * 36;
            int r    = rem >> 1;
            int side = rem & 1;
            int gy   = by - 1 + r;
            int gx   = side ? bx + 32 : bx - 1;
            bool ok  = ((unsigned)gy < (unsigned)HH) & ((unsigned)gx < (unsigned)WW);
            const float* src = xc + cc * HH * WW + (ok ? gy * WW + gx : 0);
            int sz = ok ? 4 : 0;
            CP_ASYNC4(s2u(&in_s[bi][cc][r][side ? 36 : 3]), src, sz);
        }
        for (int i = t; i < 36 * (OCB / 4); i += 128) {
            int row = i / (OCB / 4);
            int q   = i - row * (OCB / 4);
            CP_ASYNC16(s2u(&w_s[bi][row][q * 4]),
                       &wt[(c0 * 9 + row) * OP + oc0 + q * 4]);
        }
    };

    load_chunk(0, 0);
    CP_COMMIT();

    int buf = 0;
    for (int c0 = 0; c0 < CIN; c0 += 4) {
        CP_WAIT0();
        __syncthreads();
        if (c0 + 4 < CIN) { load_chunk(c0 + 4, buf ^ 1); CP_COMMIT(); }

        #pragma unroll
        for (int cc = 0; cc < 4; cc++) {
            #pragma unroll
            for (int ry = 0; ry < 3; ry++) {
                float e0 = in_s[buf][cc][ly + ry][lx * 4 + 3];
                float4 rm = *(const float4*)&in_s[buf][cc][ly + ry][lx * 4 + 4];
                float e5 = in_s[buf][cc][ly + ry][lx * 4 + 8];
                float rowv[6] = {e0, rm.x, rm.y, rm.z, rm.w, e5};
                #pragma unroll
                for (int rx = 0; rx < 3; rx++) {
                    u64 iv2[4];
                    #pragma unroll
                    for (int p = 0; p < 4; p++) PACKDUP(iv2[p], rowv[p + rx]);
                    const ulonglong2* wp2 =
                        (const ulonglong2*)&w_s[buf][cc * 9 + ry * 3 + rx][0];
                    #pragma unroll
                    for (int q2 = 0; q2 < OCB / 4; q2++) {
                        ulonglong2 ww = wp2[q2];
                        #pragma unroll
                        for (int p = 0; p < 4; p++)
                            FMA2(acc[2 * q2][p], ww.x, iv2[p], acc[2 * q2][p]);
                        #pragma unroll
                        for (int p = 0; p < 4; p++)
                            FMA2(acc[2 * q2 + 1][p], ww.y, iv2[p], acc[2 * q2 + 1][p]);
                    }
                }
            }
        }
        buf ^= 1;
    }

    const int gy = by + ly;
    const int gx = bx + lx * 4;
    #pragma unroll
    for (int q = 0; q < OCB / 2; q++) {
        float lo[4], hi[4];
        #pragma unroll
        for (int p = 0; p < 4; p++) {
            unsigned int ul, uh;
            UNPACK2(ul, uh, acc[q][p]);
            lo[p] = __uint_as_float(ul);
            hi[p] = __uint_as_float(uh);
        }
        #pragma unroll
        for (int h = 0; h < 2; h++) {
            int oc = 2 * q + h;
            if (oc0 + oc < Cout) {
                float bvv = bias[oc0 + oc];
                const float* s = h ? hi : lo;
                float v0 = s[0] + bvv, v1 = s[1] + bvv;
                float v2 = s[2] + bvv, v3 = s[3] + bvv;
                if (RELU) { v0 = lrelu(v0); v1 = lrelu(v1); v2 = lrelu(v2); v3 = lrelu(v3); }
                *(float4*)&y[((b * Cout + oc0 + oc) * HH + gy) * WW + gx] =
                    make_float4(v0, v1, v2, v3);
            }
        }
    }
}

// ---------------------------------------------------------------------------
// Deformable 3x3 conv + LeakyReLU (exact R10 measured-best form: 433us).
// 256 threads, 64 px on one row, all O channels. CC=4 chunks,
// double-buffered val + weights (cp.async), one barrier per chunk.
// ---------------------------------------------------------------------------
template<int C, int O>
__global__ __launch_bounds__(256, 4)
void dconv3x3_kernel(const float* __restrict__ x, const float* __restrict__ off,
                     const float* __restrict__ wt, const float* __restrict__ bias,
                     float* __restrict__ y)
{
    constexpr int CC = 4;
    constexpr int PX = 64;
    constexpr int KS = CC * 9;          // 36
    constexpr int NC = C / CC;
    constexpr int OT = O / 16;          // 8 (O=128) or 4 (O=64)
    constexpr int HS = HH * WW;
    extern __shared__ __align__(16) float dsm[];
    float* val_s = dsm;                 // 2 * KS * PX
    float* w_s   = dsm + 2 * KS * PX;   // 2 * KS * O

    const int t  = threadIdx.x;
    const int og = t >> 4;               // 0..15
    const int pg = t & 15;               // 0..15 (px base = pg*4)
    const int x0 = blockIdx.x * PX;
    const int yy = blockIdx.y;
    const int b  = blockIdx.z;

    const float* xb  = x + b * C * HS;
    const float* ofb = off + (b * 18 * HH + yy) * WW + x0;

    auto load_w = [&](int ci, int bi) {
        const float4* src = (const float4*)(wt + ci * KS * O);
        float* dst = w_s + bi * KS * O;
        for (int i = t; i < KS * O / 4; i += 256)
            CP_ASYNC16(s2u(dst + i * 4), src + i);
    };

    auto phaseA = [&](int ci, int bi) {
        float* dst = val_s + bi * KS * PX;
        const float* xc = xb + ci * CC * HS;
        #pragma unroll 1
        for (int j = t; j < 9 * PX; j += 256) {
            int px = j & (PX - 1);
            int k  = j >> 6;
            float dy = ofb[(2 * k) * HS + px];
            float dx = ofb[(2 * k + 1) * HS + px];
            int ky = k / 3;
            int kx = k - ky * 3;
            float py  = (float)(yy + ky - 1) + dy;
            float pxx = (float)(x0 + px + kx - 1) + dx;
            float fy = floorf(py), fx = floorf(pxx);
            int yi = (int)fy, xi = (int)fx;
            float wyv = py - fy, wxv = pxx - fx;
            bool y0in = (unsigned)yi < (unsigned)HH;
            bool y1in = (unsigned)(yi + 1) < (unsigned)HH;
            bool x0in = (unsigned)xi < (unsigned)WW;
            bool x1in = (unsigned)(xi + 1) < (unsigned)WW;
            bool ok00 = y0in & x0in, ok01 = y0in & x1in;
            bool ok10 = y1in & x0in, ok11 = y1in & x1in;
            int base = yi * WW + xi;
            float a00[CC], a01[CC], a10[CC], a11[CC];
            #pragma unroll
            for (int cc = 0; cc < CC; cc++) {
                const float* p = xc + cc * HS + base;
                a00[cc] = ok00 ? p[0]      : 0.f;
                a01[cc] = ok01 ? p[1]      : 0.f;
                a10[cc] = ok10 ? p[WW]     : 0.f;
                a11[cc] = ok11 ? p[WW + 1] : 0.f;
            }
            float* d0 = dst + k * PX + px;
            #pragma unroll
            for (int cc = 0; cc < CC; cc++) {
                float v0 = a00[cc] + (a01[cc] - a00[cc]) * wxv;
                float v1 = a10[cc] + (a11[cc] - a10[cc]) * wxv;
                d0[cc * 9 * PX] = v0 + (v1 - v0) * wyv;
            }
        }
    };

    u64 acc[OT / 2][4];
    #pragma unroll
    for (int q = 0; q < OT / 2; q++)
        #pragma unroll
        for (int p = 0; p < 4; p++) acc[q][p] = 0ull;

    // prologue
    load_w(0, 0);
    CP_COMMIT();
    phaseA(0, 0);

    for (int i = 0; i < NC; i++) {
        CP_WAIT0();
        __syncthreads();      // val(i), w(i) visible; prior buffers free
        if (i + 1 < NC) { load_w(i + 1, (i + 1) & 1); CP_COMMIT(); }

        // phase B(i)
        const float* vb = val_s + (i & 1) * KS * PX;
        const float* wb = w_s + (i & 1) * KS * O;
        #pragma unroll 4
        for (int kk = 0; kk < KS; kk++) {
            float4 v4 = *(const float4*)&vb[kk * PX + pg * 4];
            u64 vv[4];
            PACKDUP(vv[0], v4.x);
            PACKDUP(vv[1], v4.y);
            PACKDUP(vv[2], v4.z);
            PACKDUP(vv[3], v4.w);
            const ulonglong2* wp2 = (const ulonglong2*)&wb[kk * O + og * OT];
            #pragma unroll
            for (int q2 = 0; q2 < OT / 4; q2++) {
                ulonglong2 ww = wp2[q2];
                #pragma unroll
                for (int p = 0; p < 4; p++)
                    FMA2(acc[2 * q2][p], ww.x, vv[p], acc[2 * q2][p]);
                #pragma unroll
                for (int p = 0; p < 4; p++)
                    FMA2(acc[2 * q2 + 1][p], ww.y, vv[p], acc[2 * q2 + 1][p]);
            }
        }

        // phase A(i+1)
        if (i + 1 < NC) phaseA(i + 1, (i + 1) & 1);
    }

    const int gx = x0 + pg * 4;
    #pragma unroll
    for (int q = 0; q < OT / 2; q++) {
        float lo[4], hi[4];
        #pragma unroll
        for (int p = 0; p < 4; p++) {
            unsigned int ul, uh;
            UNPACK2(ul, uh, acc[q][p]);
            lo[p] = __uint_as_float(ul);
            hi[p] = __uint_as_float(uh);
        }
        #pragma unroll
        for (int h = 0; h < 2; h++) {
            int o = og * OT + 2 * q + h;
            float bvv = bias[o];
            const float* s = h ? hi : lo;
            float4 r4;
            r4.x = lrelu(s[0] + bvv);
            r4.y = lrelu(s[1] + bvv);
            r4.z = lrelu(s[2] + bvv);
            r4.w = lrelu(s[3] + bvv);
            *(float4*)&y[((b * O + o) * HH + yy) * WW + gx] = r4;
        }
    }
}

// ---------------------------------------------------------------------------
// Launch: one prep kernel (all 9 weight transposes), then 3 stages of
// conv(+leaky) -> offset conv -> deform conv(+leaky). Graph-capturable.
// Offset convs use the plain conv kernel (R10 configuration — the 2px
// offset variants of R13/R14 both measured slower).
// ---------------------------------------------------------------------------
extern "C" void kernel_launch(void* const* d_in, const int* in_sizes, int n_in,
                              void* d_out, int out_size)
{
    const float* x = (const float*)d_in[0];
    const float* p[18];
    for (int i = 0; i < 18; i++) p[i] = (const float*)d_in[1 + i];

    float *A, *Bf, *OFF;
    float (*WTC)[128 * 9 * 128], (*WTO)[128 * 9 * 24], (*WTD)[128 * 9 * 128];
    cudaGetSymbolAddress((void**)&A,   g_A);
    cudaGetSymbolAddress((void**)&Bf,  g_B);
    cudaGetSymbolAddress((void**)&OFF, g_off);
    cudaGetSymbolAddress((void**)&WTC, g_wtc);
    cudaGetSymbolAddress((void**)&WTO, g_wto);
    cudaGetSymbolAddress((void**)&WTD, g_wtd);

    // ---- prep: all weight transposes in one launch ----
    PrepJobs jobs;
    const int cin_s[3]  = {64, 128, 128};
    const int cout_s[3] = {128, 128, 64};
    for (int s = 0; s < 3; s++) {
        jobs.src[3 * s + 0] = p[6 * s + 0];
        jobs.dst[3 * s + 0] = WTC[s];
        jobs.C9[3 * s + 0] = cin_s[s] * 9;
        jobs.O[3 * s + 0] = cout_s[s];
        jobs.OP[3 * s + 0] = cout_s[s];
        jobs.src[3 * s + 1] = p[6 * s + 2];
        jobs.dst[3 * s + 1] = WTO[s];
        jobs.C9[3 * s + 1] = cout_s[s] * 9;
        jobs.O[3 * s + 1] = 18;
        jobs.OP[3 * s + 1] = 24;
        jobs.src[3 * s + 2] = p[6 * s + 4];
        jobs.dst[3 * s + 2] = WTD[s];
        jobs.C9[3 * s + 2] = cout_s[s] * 9;
        jobs.O[3 * s + 2] = cout_s[s];
        jobs.OP[3 * s + 2] = cout_s[s];
    }
    prep_kernel<<<dim3(64, 9), 256>>>(jobs);

    // dconv smem: val(2*36*64) + w(2*36*O) floats
    const int smemD128 = (2 * 36 * 64 + 2 * 36 * 128) * 4;  // 55296
    const int smemD64  = (2 * 36 * 64 + 2 * 36 * 64) * 4;   // 36864
    cudaFuncSetAttribute(dconv3x3_kernel<128, 128>,
                         cudaFuncAttributeMaxDynamicSharedMemorySize, smemD128);
    cudaFuncSetAttribute(dconv3x3_kernel<64, 64>,
                         cudaFuncAttributeMaxDynamicSharedMemorySize, smemD64);

    dim3 blk128(128), blk256(256);
    dim3 dgrid(WW / 64, HH, BB);

    // ---- stage 1: 64 -> 128 ----
    conv3x3_kernel<64, 16, true><<<dim3(4, 8, BB * 8), blk128>>>(x, WTC[0], p[1], A, 128, 128, 8);
    conv3x3_kernel<128, 8, false><<<dim3(4, 8, BB * 3), blk128>>>(A, WTO[0], p[3], OFF, 18, 24, 3);
    dconv3x3_kernel<128, 128><<<dgrid, blk256, smemD128>>>(A, OFF, WTD[0], p[5], Bf);

    // ---- stage 2: 128 -> 128 ----
    conv3x3_kernel<128, 16, true><<<dim3(4, 8, BB * 8), blk128>>>(Bf, WTC[1], p[7], A, 128, 128, 8);
    conv3x3_kernel<128, 8, false><<<dim3(4, 8, BB * 3), blk128>>>(A, WTO[1], p[9], OFF, 18, 24, 3);
    dconv3x3_kernel<128, 128><<<dgrid, blk256, smemD128>>>(A, OFF, WTD[1], p[11], Bf);

    // ---- stage 3: 128 -> 64 ----
    conv3x3_kernel<128, 16, true><<<dim3(4, 8, BB * 4), blk128>>>(Bf, WTC[2], p[13], A, 64, 64, 4);
    conv3x3_kernel<64, 8, false><<<dim3(4, 8, BB * 3), blk128>>>(A, WTO[2], p[15], OFF, 18, 24, 3);
    dconv3x3_kernel<64, 64><<<dgrid, blk256, smemD64>>>(A, OFF, WTD[2], p[17], (float*)d_out);
}